// round 16
// baseline (speedup 1.0000x reference)
#include <cuda_runtime.h>
#include <cuda_fp16.h>
#include <cstdint>
#include <cstddef>

#define N_B 2
#define L_S 2048
#define E_D 1024
#define H_N 16
#define D_H 64
// Q pre-scale: log2(e)/32 — folds 1/sqrt(E) and the exp2 conversion.
#define QSCALE 0.04508422002778f

// -------- scratch (device globals; no allocations allowed) --------
__device__ __half g_q [N_B*H_N*L_S*D_H];  // [n][h][l][d], *QSCALE
__device__ __half g_k [N_B*H_N*L_S*D_H];
__device__ float  g_v [N_B*H_N*L_S*D_H];  // fp32 (feeds transpose)
__device__ __half g_vt[N_B*H_N*L_S*D_H];  // [n][h][d][l]
__device__ __half g_ao[N_B*L_S*E_D];      // attention out [n*L+l][E], fp16
__device__ __half g_wo[E_D*E_D];          // Wo, fp16
__device__ float g_wq[D_H*D_H];
__device__ float g_wk[D_H*D_H];
__device__ float g_wv[D_H*D_H];
__device__ float g_mb[N_B*L_S];           // mask bias: 0 or -1e30

// ---------------- helpers ----------------
__device__ __forceinline__ uint32_t f2tf(float f) {
    uint32_t u; asm("cvt.rna.tf32.f32 %0, %1;" : "=r"(u) : "f"(f)); return u;
}
__device__ __forceinline__ float f2tf_f(float f) { return __uint_as_float(f2tf(f)); }
__device__ __forceinline__ float ex2(float x) {
    float y; asm("ex2.approx.f32 %0, %1;" : "=f"(y) : "f"(x)); return y;
}
__device__ __forceinline__ uint32_t pack_h2(float lo, float hi) {
    uint32_t u; asm("cvt.rn.f16x2.f32 %0, %1, %2;" : "=r"(u) : "f"(hi), "f"(lo));
    return u;
}
__device__ __forceinline__ void mma8(float* d, const uint32_t* a, const uint32_t* b) {
    asm("mma.sync.aligned.m16n8k8.row.col.f32.tf32.tf32.f32 "
        "{%0,%1,%2,%3},{%4,%5,%6,%7},{%8,%9},{%0,%1,%2,%3};"
        : "+f"(d[0]), "+f"(d[1]), "+f"(d[2]), "+f"(d[3])
        : "r"(a[0]), "r"(a[1]), "r"(a[2]), "r"(a[3]),
          "r"(b[0]), "r"(b[1]));
}
__device__ __forceinline__ void mma16(float* d, const uint32_t* a, const uint32_t* b) {
    asm("mma.sync.aligned.m16n8k16.row.col.f32.f16.f16.f32 "
        "{%0,%1,%2,%3},{%4,%5,%6,%7},{%8,%9},{%0,%1,%2,%3};"
        : "+f"(d[0]), "+f"(d[1]), "+f"(d[2]), "+f"(d[3])
        : "r"(a[0]), "r"(a[1]), "r"(a[2]), "r"(a[3]),
          "r"(b[0]), "r"(b[1]));
}
__device__ __forceinline__ void ldsm4(uint32_t* r, uint32_t addr) {
    asm volatile("ldmatrix.sync.aligned.m8n8.x4.shared.b16 {%0,%1,%2,%3}, [%4];"
        : "=r"(r[0]), "=r"(r[1]), "=r"(r[2]), "=r"(r[3]) : "r"(addr));
}
__device__ __forceinline__ void cp16(uint32_t dst, const void* src) {
    asm volatile("cp.async.ca.shared.global [%0], [%1], 16;" :: "r"(dst), "l"(src));
}
#define CP_COMMIT() asm volatile("cp.async.commit_group;")
#define CP_WAIT0()  asm volatile("cp.async.wait_group 0;")
// f16 m16n8k16 frag layout (g=lane>>2, q=lane&3):
//  A: a0=(g,2q:2q+1) a1=(g+8,..) a2=(g,2q+8:..) a3=(g+8,2q+8:..)
//  B: b0=(k=2q:2q+1,n=g) b1=(k=2q+8:..,n=g)
//  C: c0=(g,2q) c1=(g,2q+1) c2=(g+8,2q) c3=(g+8,2q+1)
// C->A identity: S C-frags (n-groups 2ck,2ck+1) pack into PV A-frag k-group ck.
// LDSM .x4 b16 lane bases:
//  A-type: row=(l&7)+((l>>3)&1)*8, col16B=(l>>4)
//  B-type: row=(l&7)+((l>>4)&1)*8, col16B=(l>>3)&1

// ============================================================================
// Kernel 0 (merged prep): TF32-round Wq/Wk/Wv, mask->bias, Wo -> fp16.
// ============================================================================
__global__ __launch_bounds__(256) void prep_kernel(
    const float* __restrict__ Wq, const float* __restrict__ Wk,
    const float* __restrict__ Wv, const float* __restrict__ Wo,
    const int* __restrict__ mask)
{
    int b = blockIdx.x, tid = threadIdx.x;
    if (b < 12) {
        int i = b * 256 + tid;
        int which = i >> 10, j = i & 1023;
        const float4* src = (const float4*)(which == 0 ? Wq : (which == 1 ? Wk : Wv));
        float4* dst = (float4*)(which == 0 ? g_wq : (which == 1 ? g_wk : g_wv));
        float4 v = src[j];
        v.x = f2tf_f(v.x); v.y = f2tf_f(v.y); v.z = f2tf_f(v.z); v.w = f2tf_f(v.w);
        dst[j] = v;
    } else if (b < 28) {
        int i = (b - 12) * 256 + tid;
        g_mb[i] = mask[i] ? 0.f : -1.0e30f;
    } else {
        int i = (b - 28) * 256 + tid;
        float4 v = ((const float4*)Wo)[i];
        uint2 o;
        o.x = pack_h2(v.x, v.y);
        o.y = pack_h2(v.z, v.w);
        ((uint2*)g_wo)[i] = o;
    }
}

// ============================================================================
// Kernel 1: QKV projection (TF32 mma). V -> fp32; Q (*QSCALE), K -> fp16.
// ============================================================================
__global__ __launch_bounds__(256) void proj_mma(
    const float* __restrict__ vals, const float* __restrict__ keys,
    const float* __restrict__ qry)
{
    const float* X; const float* Wc; float oscale;
    int which = blockIdx.y;
    if (which == 0)      { X = vals; Wc = g_wv; oscale = 1.f; }
    else if (which == 1) { X = keys; Wc = g_wk; oscale = 1.f; }
    else                 { X = qry;  Wc = g_wq; oscale = QSCALE; }

    __shared__ float Xs[2][64*68];

    int rowBase0 = blockIdx.x * 256;
    int tid = threadIdx.x, warp = tid >> 5, lane = tid & 31;
    int g = lane >> 2, q = lane & 3;
    int wm = warp & 3, wn = warp >> 2;

    uint32_t wb[8][4][2];
    #pragma unroll
    for (int kk = 0; kk < 8; kk++)
        #pragma unroll
        for (int nf2 = 0; nf2 < 4; nf2++) {
            int nn = wn*32 + nf2*8 + g;
            wb[kk][nf2][0] = __float_as_uint(__ldg(&Wc[nn*64 + kk*8 + q    ]));
            wb[kk][nf2][1] = __float_as_uint(__ldg(&Wc[nn*64 + kk*8 + q + 4]));
        }

    uint32_t xs_u = (uint32_t)__cvta_generic_to_shared(Xs);

    {
        const float4* Xg = (const float4*)(X + (size_t)rowBase0 * 64);
        for (int i = tid; i < 1024; i += 256) {
            int r = i >> 4, c4 = (i & 15) << 2;
            cp16(xs_u + (r*68 + c4)*4, Xg + i);
        }
        CP_COMMIT();
    }

    for (int rt = 0; rt < 4; rt++) {
        CP_WAIT0();
        __syncthreads();

        if (rt + 1 < 4) {
            const float4* Xg = (const float4*)(X + (size_t)(rowBase0 + (rt+1)*64) * 64);
            uint32_t xo = xs_u + ((rt+1)&1) * 64*68*4;
            for (int i = tid; i < 1024; i += 256) {
                int r = i >> 4, c4 = (i & 15) << 2;
                cp16(xo + (r*68 + c4)*4, Xg + i);
            }
            CP_COMMIT();
        }
        const float* Xc = Xs[rt & 1];

        float acc[4][4];
        #pragma unroll
        for (int nf2 = 0; nf2 < 4; nf2++)
            #pragma unroll
            for (int t = 0; t < 4; t++) acc[nf2][t] = 0.f;

        #pragma unroll
        for (int kk = 0; kk < 8; kk++) {
            uint32_t a[4];
            a[0] = f2tf(Xc[(wm*16+g  )*68 + kk*8 + q    ]);
            a[1] = f2tf(Xc[(wm*16+g+8)*68 + kk*8 + q    ]);
            a[2] = f2tf(Xc[(wm*16+g  )*68 + kk*8 + q + 4]);
            a[3] = f2tf(Xc[(wm*16+g+8)*68 + kk*8 + q + 4]);
            #pragma unroll
            for (int nf2 = 0; nf2 < 4; nf2++)
                mma8(acc[nf2], a, wb[kk][nf2]);
        }

        int r0 = rowBase0 + rt*64 + wm*16 + g;
        int r1 = r0 + 8;
        int h0 = r0 & 15, nl0 = r0 >> 4;
        int h1 = r1 & 15, nl1 = r1 >> 4;
        size_t base0 = (((size_t)((nl0 >> 11)*H_N + h0))*L_S + (nl0 & (L_S-1)))*D_H;
        size_t base1 = (((size_t)((nl1 >> 11)*H_N + h1))*L_S + (nl1 & (L_S-1)))*D_H;
        if (which == 0) {
            #pragma unroll
            for (int nf2 = 0; nf2 < 4; nf2++) {
                int c = wn*32 + nf2*8 + 2*q;
                *(float2*)&g_v[base0 + c] = make_float2(acc[nf2][0], acc[nf2][1]);
                *(float2*)&g_v[base1 + c] = make_float2(acc[nf2][2], acc[nf2][3]);
            }
        } else {
            __half* Yh = (which == 1) ? g_k : g_q;
            #pragma unroll
            for (int nf2 = 0; nf2 < 4; nf2++) {
                int c = wn*32 + nf2*8 + 2*q;
                *(uint32_t*)&Yh[base0 + c] = pack_h2(acc[nf2][0]*oscale, acc[nf2][1]*oscale);
                *(uint32_t*)&Yh[base1 + c] = pack_h2(acc[nf2][2]*oscale, acc[nf2][3]*oscale);
            }
        }
    }
}

// ============================================================================
// Kernel 1b: transpose V per head: fp32 [l][d] -> fp16 [d][l]
// ============================================================================
__global__ __launch_bounds__(256) void transpose_v_kernel()
{
    __shared__ float ts[64][65];
    int lt = blockIdx.x * 64;
    int nh = blockIdx.y;
    int tid = threadIdx.x;

    const float* src = g_v + (size_t)nh * L_S * D_H + (size_t)lt * D_H;
    for (int i = tid; i < 1024; i += 256) {
        int r = i >> 4, c4 = (i & 15) << 2;
        float4 v = *(const float4*)&src[r*64 + c4];
        ts[r][c4+0] = v.x; ts[r][c4+1] = v.y; ts[r][c4+2] = v.z; ts[r][c4+3] = v.w;
    }
    __syncthreads();

    __half* dst = g_vt + (size_t)nh * L_S * D_H;
    for (int i = tid; i < 1024; i += 256) {
        int d = i >> 4, l4 = (i & 15) << 2;
        uint2 o;
        o.x = pack_h2(ts[l4+0][d], ts[l4+1][d]);
        o.y = pack_h2(ts[l4+2][d], ts[l4+3][d]);
        *(uint2*)&dst[(size_t)d * L_S + lt + l4] = o;
    }
}

// ============================================================================
// Kernel 2: flash attention, fp16, q-tile 64, 128 threads.
// 2m x 2n warp tiling: warp (wm, wn) owns q-rows wm*32..+31, k-cols wn*32..+31.
// K and V LDSM traffic HALVED vs m-only tiling. P in registers (C->A identity).
// O / row-sum partials pair-reduced across wn once at the end via smem.
// ============================================================================
#define KSTR 72
#define VSTR 72

__global__ __launch_bounds__(128, 3) void attn_mma()
{
    extern __shared__ __half smh[];
    __half* Ksb = smh;                  // [2][64*KSTR]  K: [c][e]
    __half* Vsb = smh + 2*64*KSTR;      // [2][64*VSTR]  Vt: [d][c]
    __half* Qs  = Vsb + 2*64*VSTR;      // [64*72]       Q staging
    float* red  = (float*)smh;          // end-of-kernel reduction (K region dead)

    int qt = blockIdx.x, h = blockIdx.y, n = blockIdx.z;
    int tid = threadIdx.x, warp = tid >> 5, lane = tid & 31;
    int g = lane >> 2, q = lane & 3;
    int wm = warp & 1, wn = warp >> 1;

    const __half* Qg  = g_q  + ((size_t)(n*H_N + h) * L_S + qt*64) * D_H;
    const __half* Kg  = g_k  +  (size_t)(n*H_N + h) * L_S * D_H;
    const __half* Vtg = g_vt +  (size_t)(n*H_N + h) * L_S * D_H;
    const float* mb  = g_mb + n * L_S;

    uint32_t ks_u = (uint32_t)__cvta_generic_to_shared(Ksb);
    uint32_t vs_u = (uint32_t)__cvta_generic_to_shared(Vsb);
    uint32_t qs_u = (uint32_t)__cvta_generic_to_shared(Qs);

    uint32_t bRow = (lane&7) + ((lane>>4)&1)*8;
    uint32_t bCol = ((lane>>3)&1)*16;
    uint32_t addrK = ks_u + bRow*KSTR*2 + bCol + (wn*32)*KSTR*2; // + col-half rows
    uint32_t addrV = vs_u + bRow*VSTR*2 + bCol + wn*64;          // + col-half bytes
    uint32_t aRow = (lane&7) + ((lane>>3)&1)*8;
    uint32_t aCol = (lane>>4)*16;
    uint32_t addrQ = qs_u + aRow*72*2 + aCol;

    // prefetch K/V tile 0
    {
        for (int i = tid; i < 1024; i += 128) {
            int i2 = i & 511;
            int r = i2 >> 3, c8 = (i2 & 7) << 3;
            if (i < 512) cp16(ks_u + (r*KSTR + c8)*2, Kg + r*64 + c8);
            else         cp16(vs_u + (r*VSTR + c8)*2, Vtg + (size_t)r*L_S + c8);
        }
        CP_COMMIT();
    }

    // stage Q (64 rows x 128 B)
    for (int i = tid; i < 512; i += 128) {
        int r = i >> 3, c8 = (i & 7) << 3;
        *(float4*)&Qs[r*72 + c8] = *(const float4*)&Qg[r*64 + c8];
    }
    __syncthreads();

    uint32_t qa[2][4][4];
    #pragma unroll
    for (int mi = 0; mi < 2; mi++)
        #pragma unroll
        for (int kk = 0; kk < 4; kk++)
            ldsm4(qa[mi][kk], addrQ + (wm*32 + mi*16)*72*2 + kk*32);

    float O[2][8][4];                 // partial over this warp's 32 k-cols
    #pragma unroll
    for (int mi = 0; mi < 2; mi++)
        #pragma unroll
        for (int nf = 0; nf < 8; nf++)
            #pragma unroll
            for (int t = 0; t < 4; t++) O[mi][nf][t] = 0.f;
    float psacc[2][2] = {{0.f,0.f},{0.f,0.f}};
    float sacc[2][4][4];

    for (int kt = 0; kt < L_S/64; kt++) {
        CP_WAIT0();
        __syncthreads();            // K/V(kt) visible; all warps past iter kt-1

        if (kt + 1 < L_S/64) {
            uint32_t ko = ks_u + ((kt+1)&1) * 64*KSTR*2;
            uint32_t vo = vs_u + ((kt+1)&1) * 64*VSTR*2;
            const __half* Ksrc = Kg + (size_t)(kt+1)*4096;
            const __half* Vsrc = Vtg + (size_t)(kt+1)*64;
            for (int i = tid; i < 1024; i += 128) {
                int i2 = i & 511;
                int r = i2 >> 3, c8 = (i2 & 7) << 3;
                if (i < 512) cp16(ko + (r*KSTR + c8)*2, Ksrc + r*64 + c8);
                else         cp16(vo + (r*VSTR + c8)*2, Vsrc + (size_t)r*L_S + c8);
            }
            CP_COMMIT();
        }
        uint32_t kbuf = addrK + (kt&1) * 64*KSTR*2;
        uint32_t vbuf = addrV + (kt&1) * 64*VSTR*2;

        // ---- S = Q K^T on this warp's 32x32 tile ----
        #pragma unroll
        for (int mi = 0; mi < 2; mi++)
            #pragma unroll
            for (int nf = 0; nf < 4; nf++)
                #pragma unroll
                for (int t = 0; t < 4; t++) sacc[mi][nf][t] = 0.f;
        #pragma unroll
        for (int kk = 0; kk < 4; kk++) {
            #pragma unroll
            for (int nfp = 0; nfp < 2; nfp++) {
                uint32_t kb[4];
                ldsm4(kb, kbuf + nfp*16*KSTR*2 + kk*32);
                mma16(sacc[0][2*nfp  ], qa[0][kk], kb    );
                mma16(sacc[1][2*nfp  ], qa[1][kk], kb    );
                mma16(sacc[0][2*nfp+1], qa[0][kk], kb + 2);
                mma16(sacc[1][2*nfp+1], qa[1][kk], kb + 2);
            }
        }

        // ---- p = exp2(s + bias), partial row sums ----
        #pragma unroll
        for (int nf = 0; nf < 4; nf++) {
            float2 m2 = *(const float2*)&mb[kt*64 + wn*32 + nf*8 + 2*q];
            #pragma unroll
            for (int mi = 0; mi < 2; mi++) {
                float p0 = ex2(sacc[mi][nf][0] + m2.x);
                float p1 = ex2(sacc[mi][nf][1] + m2.y);
                float p2 = ex2(sacc[mi][nf][2] + m2.x);
                float p3 = ex2(sacc[mi][nf][3] + m2.y);
                psacc[mi][0] += p0 + p1;
                psacc[mi][1] += p2 + p3;
                sacc[mi][nf][0] = p0; sacc[mi][nf][1] = p1;
                sacc[mi][nf][2] = p2; sacc[mi][nf][3] = p3;
            }
        }

        // ---- O += P @ V over this warp's 32-k slice ----
        #pragma unroll
        for (int ck = 0; ck < 2; ck++) {
            uint32_t pa[2][4];
            #pragma unroll
            for (int mi = 0; mi < 2; mi++) {
                pa[mi][0] = pack_h2(sacc[mi][2*ck  ][0], sacc[mi][2*ck  ][1]);
                pa[mi][1] = pack_h2(sacc[mi][2*ck  ][2], sacc[mi][2*ck  ][3]);
                pa[mi][2] = pack_h2(sacc[mi][2*ck+1][0], sacc[mi][2*ck+1][1]);
                pa[mi][3] = pack_h2(sacc[mi][2*ck+1][2], sacc[mi][2*ck+1][3]);
            }
            #pragma unroll
            for (int nfp = 0; nfp < 4; nfp++) {
                uint32_t vb[4];
                ldsm4(vb, vbuf + nfp*16*VSTR*2 + ck*32);
                mma16(O[0][2*nfp  ], pa[0], vb    );
                mma16(O[1][2*nfp  ], pa[1], vb    );
                mma16(O[0][2*nfp+1], pa[0], vb + 2);
                mma16(O[1][2*nfp+1], pa[1], vb + 2);
            }
        }
    }

    // ---- quad-reduce partial row sums within warp ----
    #pragma unroll
    for (int mi = 0; mi < 2; mi++)
        #pragma unroll
        for (int hf = 0; hf < 2; hf++) {
            float v = psacc[mi][hf];
            v += __shfl_xor_sync(0xffffffffu, v, 1);
            v += __shfl_xor_sync(0xffffffffu, v, 2);
            psacc[mi][hf] = v;
        }

    // ---- cross-warp (wn) pair reduction via smem (K region now dead) ----
    __syncthreads();    // all K/V smem reads complete
    if (wn == 1) {
        float* dst = red + (wm*32 + lane) * 68;
        #pragma unroll
        for (int mi = 0; mi < 2; mi++)
            #pragma unroll
            for (int nf = 0; nf < 8; nf++)
                #pragma unroll
                for (int t = 0; t < 4; t++)
                    dst[mi*32 + nf*4 + t] = O[mi][nf][t];
        dst[64] = psacc[0][0]; dst[65] = psacc[0][1];
        dst[66] = psacc[1][0]; dst[67] = psacc[1][1];
    }
    __syncthreads();
    if (wn == 0) {
        const float* src = red + (wm*32 + lane) * 68;
        #pragma unroll
        for (int mi = 0; mi < 2; mi++)
            #pragma unroll
            for (int nf = 0; nf < 8; nf++)
                #pragma unroll
                for (int t = 0; t < 4; t++)
                    O[mi][nf][t] += src[mi*32 + nf*4 + t];
        psacc[0][0] += src[64]; psacc[0][1] += src[65];
        psacc[1][0] += src[66]; psacc[1][1] += src[67];

        #pragma unroll
        for (int mi = 0; mi < 2; mi++) {
            float invl0 = 1.0f / psacc[mi][0];
            float invl1 = 1.0f / psacc[mi][1];
            size_t row0 = ((size_t)n*L_S + qt*64 + wm*32 + mi*16 + g    ) * E_D + h*D_H;
            size_t row1 = ((size_t)n*L_S + qt*64 + wm*32 + mi*16 + g + 8) * E_D + h*D_H;
            #pragma unroll
            for (int nf = 0; nf < 8; nf++) {
                int c = nf*8 + 2*q;
                *(uint32_t*)&g_ao[row0 + c] = pack_h2(O[mi][nf][0]*invl0, O[mi][nf][1]*invl0);
                *(uint32_t*)&g_ao[row1 + c] = pack_h2(O[mi][nf][2]*invl1, O[mi][nf][3]*invl1);
            }
        }
    }
}

// ============================================================================
// Kernel 3: out = A @ Wo^T + bo, fp16 m16n8k16. 128x128 tile, BK=32,
// 128 threads (2m x 2n warps, m64 x n64 warp tile).
// ============================================================================
#define GSTR 40   // halves per row (32 data + 8 pad)

__global__ __launch_bounds__(128) void out_gemm_mma(
    const float* __restrict__ bo, float* __restrict__ out)
{
    extern __shared__ __half smg[];
    __half* As = smg;               // [2][128*GSTR]
    __half* Bs = smg + 2*128*GSTR;  // [2][128*GSTR]

    int nt = blockIdx.x * 128;
    int mt = blockIdx.y * 128;
    int tid = threadIdx.x, warp = tid >> 5, lane = tid & 31;
    int g = lane >> 2, q = lane & 3;
    int wm = warp & 1, wn = warp >> 1;

    uint32_t as_u = (uint32_t)__cvta_generic_to_shared(As);
    uint32_t bs_u = (uint32_t)__cvta_generic_to_shared(Bs);

    uint32_t aRow = (lane&7) + ((lane>>3)&1)*8;
    uint32_t aCol = (lane>>4)*16;
    uint32_t addrA = as_u + aRow*GSTR*2 + aCol;
    uint32_t bRow = (lane&7) + ((lane>>4)&1)*8;
    uint32_t bCol = ((lane>>3)&1)*16;
    uint32_t addrB = bs_u + bRow*GSTR*2 + bCol;

    float acc[4][8][4];
    #pragma unroll
    for (int mi = 0; mi < 4; mi++)
        #pragma unroll
        for (int nf = 0; nf < 8; nf++)
            #pragma unroll
            for (int t = 0; t < 4; t++) acc[mi][nf][t] = 0.f;

    for (int i = tid; i < 1024; i += 128) {
        int i2 = i & 511;
        int r = i2 >> 2, c8 = (i2 & 3) << 3;
        if (i < 512) cp16(as_u + (r*GSTR + c8)*2, &g_ao[(size_t)(mt + r)*E_D + c8]);
        else         cp16(bs_u + (r*GSTR + c8)*2, &g_wo[(size_t)(nt + r)*E_D + c8]);
    }
    CP_COMMIT();

    for (int t = 0; t < E_D/32; t++) {
        CP_WAIT0();
        __syncthreads();

        if (t + 1 < E_D/32) {
            int kt = (t + 1) * 32;
            uint32_t ao  = as_u + ((t+1)&1) * 128*GSTR*2;
            uint32_t bou = bs_u + ((t+1)&1) * 128*GSTR*2;
            for (int i = tid; i < 1024; i += 128) {
                int i2 = i & 511;
                int r = i2 >> 2, c8 = (i2 & 3) << 3;
                if (i < 512) cp16(ao  + (r*GSTR + c8)*2, &g_ao[(size_t)(mt + r)*E_D + kt + c8]);
                else         cp16(bou + (r*GSTR + c8)*2, &g_wo[(size_t)(nt + r)*E_D + kt + c8]);
            }
            CP_COMMIT();
        }
        uint32_t abuf = addrA + (t&1) * 128*GSTR*2;
        uint32_t bbuf = addrB + (t&1) * 128*GSTR*2;

        #pragma unroll
        for (int kk = 0; kk < 2; kk++) {
            uint32_t a[4][4];
            #pragma unroll
            for (int mi = 0; mi < 4; mi++)
                ldsm4(a[mi], abuf + (wm*64 + mi*16)*GSTR*2 + kk*32);
            #pragma unroll
            for (int nfp = 0; nfp < 4; nfp++) {
                uint32_t b[4];
                ldsm4(b, bbuf + (wn*64 + nfp*16)*GSTR*2 + kk*32);
                #pragma unroll
                for (int mi = 0; mi < 4; mi++) {
                    mma16(acc[mi][2*nfp  ], a[mi], b    );
                    mma16(acc[mi][2*nfp+1], a[mi], b + 2);
                }
            }
        }
    }

    #pragma unroll
    for (int mi = 0; mi < 4; mi++) {
        size_t row0 = (size_t)(mt + wm*64 + mi*16 + g    ) * E_D + nt;
        size_t row1 = (size_t)(mt + wm*64 + mi*16 + g + 8) * E_D + nt;
        #pragma unroll
        for (int nf = 0; nf < 8; nf++) {
            int c = wn*64 + nf*8 + 2*q;
            float2 bb = *(const float2*)&bo[nt + c];
            *(float2*)&out[row0 + c] =
                make_float2(acc[mi][nf][0] + bb.x, acc[mi][nf][1] + bb.y);
            *(float2*)&out[row1 + c] =
                make_float2(acc[mi][nf][2] + bb.x, acc[mi][nf][3] + bb.y);
        }
    }
}

// ============================================================================
extern "C" void kernel_launch(void* const* d_in, const int* in_sizes, int n_in,
                              void* d_out, int out_size)
{
    const float* values = (const float*)d_in[0];
    const float* keysp  = (const float*)d_in[1];
    const float* query  = (const float*)d_in[2];
    const int*   mask   = (const int*)  d_in[3];
    const float* Wv     = (const float*)d_in[4];
    const float* Wk     = (const float*)d_in[5];
    const float* Wq     = (const float*)d_in[6];
    const float* Wo     = (const float*)d_in[7];
    const float* bo     = (const float*)d_in[8];
    float* out = (float*)d_out;

    // 0. merged prep
    prep_kernel<<<28 + E_D*E_D/4/256, 256>>>(Wq, Wk, Wv, Wo, mask);

    // 1. QKV projections (Q/K -> fp16), then V transpose (-> fp16 [d][l])
    proj_mma<<<dim3((N_B*L_S*H_N)/256, 3), 256>>>(values, keysp, query);
    transpose_v_kernel<<<dim3(L_S/64, N_B*H_N), 256>>>();

    // 2. flash attention (2m x 2n warp tiling, ~45 KB dynamic smem, 3 blocks/SM)
    int smem_attn = (2*64*KSTR + 2*64*VSTR + 64*72) * 2;
    cudaFuncSetAttribute(attn_mma,
                         cudaFuncAttributeMaxDynamicSharedMemorySize, smem_attn);
    attn_mma<<<dim3(L_S/64, H_N, N_B), 128, smem_attn>>>();

    // 3. output projection + bias (fp16, 40 KB dynamic smem)
    int smem_og = 4*128*GSTR * 2;
    cudaFuncSetAttribute(out_gemm_mma,
                         cudaFuncAttributeMaxDynamicSharedMemorySize, smem_og);
    out_gemm_mma<<<dim3(E_D/128, (N_B*L_S)/128), 128, smem_og>>>(bo, out);
}

// round 17
// speedup vs baseline: 1.0514x; 1.0514x over previous
#include <cuda_runtime.h>
#include <cuda_fp16.h>
#include <cstdint>
#include <cstddef>

#define N_B 2
#define L_S 2048
#define E_D 1024
#define H_N 16
#define D_H 64
// Q pre-scale: log2(e)/32 — folds 1/sqrt(E) and the exp2 conversion.
#define QSCALE 0.04508422002778f

// -------- scratch (device globals; no allocations allowed) --------
__device__ __half g_q [N_B*H_N*L_S*D_H];  // [n][h][l][d], *QSCALE
__device__ __half g_k [N_B*H_N*L_S*D_H];
__device__ __half g_vt[N_B*H_N*L_S*D_H];  // [n][h][d][l] (written by proj directly)
__device__ __half g_ao[N_B*L_S*E_D];      // attention out [n*L+l][E], fp16
__device__ __half g_wo[E_D*E_D];          // Wo, fp16
__device__ float g_wq[D_H*D_H];
__device__ float g_wk[D_H*D_H];
__device__ float g_wv[D_H*D_H];
__device__ float g_mb[N_B*L_S];           // mask bias: 0 or -1e30

// ---------------- helpers ----------------
__device__ __forceinline__ uint32_t f2tf(float f) {
    uint32_t u; asm("cvt.rna.tf32.f32 %0, %1;" : "=r"(u) : "f"(f)); return u;
}
__device__ __forceinline__ float f2tf_f(float f) { return __uint_as_float(f2tf(f)); }
__device__ __forceinline__ float ex2(float x) {
    float y; asm("ex2.approx.f32 %0, %1;" : "=f"(y) : "f"(x)); return y;
}
__device__ __forceinline__ uint32_t pack_h2(float lo, float hi) {
    uint32_t u; asm("cvt.rn.f16x2.f32 %0, %1, %2;" : "=r"(u) : "f"(hi), "f"(lo));
    return u;
}
__device__ __forceinline__ void mma8(float* d, const uint32_t* a, const uint32_t* b) {
    asm("mma.sync.aligned.m16n8k8.row.col.f32.tf32.tf32.f32 "
        "{%0,%1,%2,%3},{%4,%5,%6,%7},{%8,%9},{%0,%1,%2,%3};"
        : "+f"(d[0]), "+f"(d[1]), "+f"(d[2]), "+f"(d[3])
        : "r"(a[0]), "r"(a[1]), "r"(a[2]), "r"(a[3]),
          "r"(b[0]), "r"(b[1]));
}
__device__ __forceinline__ void mma16(float* d, const uint32_t* a, const uint32_t* b) {
    asm("mma.sync.aligned.m16n8k16.row.col.f32.f16.f16.f32 "
        "{%0,%1,%2,%3},{%4,%5,%6,%7},{%8,%9},{%0,%1,%2,%3};"
        : "+f"(d[0]), "+f"(d[1]), "+f"(d[2]), "+f"(d[3])
        : "r"(a[0]), "r"(a[1]), "r"(a[2]), "r"(a[3]),
          "r"(b[0]), "r"(b[1]));
}
__device__ __forceinline__ void ldsm4(uint32_t* r, uint32_t addr) {
    asm volatile("ldmatrix.sync.aligned.m8n8.x4.shared.b16 {%0,%1,%2,%3}, [%4];"
        : "=r"(r[0]), "=r"(r[1]), "=r"(r[2]), "=r"(r[3]) : "r"(addr));
}
__device__ __forceinline__ void cp16(uint32_t dst, const void* src) {
    asm volatile("cp.async.ca.shared.global [%0], [%1], 16;" :: "r"(dst), "l"(src));
}
#define CP_COMMIT() asm volatile("cp.async.commit_group;")
#define CP_WAIT0()  asm volatile("cp.async.wait_group 0;")
// f16 m16n8k16 frag layout (g=lane>>2, q=lane&3):
//  A: a0=(g,2q:2q+1) a1=(g+8,..) a2=(g,2q+8:..) a3=(g+8,2q+8:..)
//  B: b0=(k=2q:2q+1,n=g) b1=(k=2q+8:..,n=g)
//  C: c0=(g,2q) c1=(g,2q+1) c2=(g+8,2q) c3=(g+8,2q+1)
// C->A identity: S C-frags (n-groups 2ck,2ck+1) pack into PV A-frag k-group ck.
// LDSM .x4 b16 lane bases:
//  A-type: row=(l&7)+((l>>3)&1)*8, col16B=(l>>4)
//  B-type: row=(l&7)+((l>>4)&1)*8, col16B=(l>>3)&1

// ============================================================================
// Kernel 0 (merged prep): TF32-round Wq/Wk/Wv, mask->bias, Wo -> fp16.
// ============================================================================
__global__ __launch_bounds__(256) void prep_kernel(
    const float* __restrict__ Wq, const float* __restrict__ Wk,
    const float* __restrict__ Wv, const float* __restrict__ Wo,
    const int* __restrict__ mask)
{
    int b = blockIdx.x, tid = threadIdx.x;
    if (b < 12) {
        int i = b * 256 + tid;
        int which = i >> 10, j = i & 1023;
        const float4* src = (const float4*)(which == 0 ? Wq : (which == 1 ? Wk : Wv));
        float4* dst = (float4*)(which == 0 ? g_wq : (which == 1 ? g_wk : g_wv));
        float4 v = src[j];
        v.x = f2tf_f(v.x); v.y = f2tf_f(v.y); v.z = f2tf_f(v.z); v.w = f2tf_f(v.w);
        dst[j] = v;
    } else if (b < 28) {
        int i = (b - 12) * 256 + tid;
        g_mb[i] = mask[i] ? 0.f : -1.0e30f;
    } else {
        int i = (b - 28) * 256 + tid;
        float4 v = ((const float4*)Wo)[i];
        uint2 o;
        o.x = pack_h2(v.x, v.y);
        o.y = pack_h2(v.z, v.w);
        ((uint2*)g_wo)[i] = o;
    }
}

// ============================================================================
// Kernel 1: QKV projection (TF32 mma). Q (*QSCALE) / K -> fp16 [l][d];
// V -> fp16 TRANSPOSED [d][l] directly via smem transpose buffer
// (fuses the former transpose kernel; same fp32->fp16 rounding point).
//
// Block covers 256 rows = 16 l-values x 16 heads (h = row & 15, since H=16).
// Warp (wm, wn), lane (g, q): row0 = base + rt*64 + wm*16 + g -> h0 = g,
// row1 = row0 + 8 -> h1 = g + 8; l_local = rt*4 + wm for both.
// tb layout: [h][d][l_local], per-h stride 1032 halves (1024 + 8 pad:
// -> g-lanes map to distinct banks, rows stay 16B-aligned for uint4 flush).
// ============================================================================
#define TBH 1032   // per-h stride in halves

__global__ __launch_bounds__(256) void proj_mma(
    const float* __restrict__ vals, const float* __restrict__ keys,
    const float* __restrict__ qry)
{
    extern __shared__ char psm[];
    float*  Xs = (float*)psm;                       // [2][64*68]
    __half* tb = (__half*)(psm + 2*64*68*4);        // [16][TBH]

    const float* X; const float* Wc; float oscale;
    int which = blockIdx.y;
    if (which == 0)      { X = vals; Wc = g_wv; oscale = 1.f; }
    else if (which == 1) { X = keys; Wc = g_wk; oscale = 1.f; }
    else                 { X = qry;  Wc = g_wq; oscale = QSCALE; }

    int rowBase0 = blockIdx.x * 256;
    int tid = threadIdx.x, warp = tid >> 5, lane = tid & 31;
    int g = lane >> 2, q = lane & 3;
    int wm = warp & 3, wn = warp >> 2;

    uint32_t wb[8][4][2];
    #pragma unroll
    for (int kk = 0; kk < 8; kk++)
        #pragma unroll
        for (int nf2 = 0; nf2 < 4; nf2++) {
            int nn = wn*32 + nf2*8 + g;
            wb[kk][nf2][0] = __float_as_uint(__ldg(&Wc[nn*64 + kk*8 + q    ]));
            wb[kk][nf2][1] = __float_as_uint(__ldg(&Wc[nn*64 + kk*8 + q + 4]));
        }

    uint32_t xs_u = (uint32_t)__cvta_generic_to_shared(Xs);

    {
        const float4* Xg = (const float4*)(X + (size_t)rowBase0 * 64);
        for (int i = tid; i < 1024; i += 256) {
            int r = i >> 4, c4 = (i & 15) << 2;
            cp16(xs_u + (r*68 + c4)*4, Xg + i);
        }
        CP_COMMIT();
    }

    for (int rt = 0; rt < 4; rt++) {
        CP_WAIT0();
        __syncthreads();

        if (rt + 1 < 4) {
            const float4* Xg = (const float4*)(X + (size_t)(rowBase0 + (rt+1)*64) * 64);
            uint32_t xo = xs_u + ((rt+1)&1) * 64*68*4;
            for (int i = tid; i < 1024; i += 256) {
                int r = i >> 4, c4 = (i & 15) << 2;
                cp16(xo + (r*68 + c4)*4, Xg + i);
            }
            CP_COMMIT();
        }
        const float* Xc = Xs + (rt & 1) * 64*68;

        float acc[4][4];
        #pragma unroll
        for (int nf2 = 0; nf2 < 4; nf2++)
            #pragma unroll
            for (int t = 0; t < 4; t++) acc[nf2][t] = 0.f;

        #pragma unroll
        for (int kk = 0; kk < 8; kk++) {
            uint32_t a[4];
            a[0] = f2tf(Xc[(wm*16+g  )*68 + kk*8 + q    ]);
            a[1] = f2tf(Xc[(wm*16+g+8)*68 + kk*8 + q    ]);
            a[2] = f2tf(Xc[(wm*16+g  )*68 + kk*8 + q + 4]);
            a[3] = f2tf(Xc[(wm*16+g+8)*68 + kk*8 + q + 4]);
            #pragma unroll
            for (int nf2 = 0; nf2 < 4; nf2++)
                mma8(acc[nf2], a, wb[kk][nf2]);
        }

        if (which == 0) {
            // V: stash fp16 into transpose buffer (flushed after loop)
            int lt = rt*4 + wm;
            #pragma unroll
            for (int nf2 = 0; nf2 < 4; nf2++) {
                int c = wn*32 + nf2*8 + 2*q;
                tb[ g     *TBH + (c  )*16 + lt] = __float2half(acc[nf2][0]);
                tb[ g     *TBH + (c+1)*16 + lt] = __float2half(acc[nf2][1]);
                tb[(g+8)  *TBH + (c  )*16 + lt] = __float2half(acc[nf2][2]);
                tb[(g+8)  *TBH + (c+1)*16 + lt] = __float2half(acc[nf2][3]);
            }
        } else {
            int r0 = rowBase0 + rt*64 + wm*16 + g;
            int r1 = r0 + 8;
            int h0 = r0 & 15, nl0 = r0 >> 4;
            int h1 = r1 & 15, nl1 = r1 >> 4;
            size_t base0 = (((size_t)((nl0 >> 11)*H_N + h0))*L_S + (nl0 & (L_S-1)))*D_H;
            size_t base1 = (((size_t)((nl1 >> 11)*H_N + h1))*L_S + (nl1 & (L_S-1)))*D_H;
            __half* Yh = (which == 1) ? g_k : g_q;
            #pragma unroll
            for (int nf2 = 0; nf2 < 4; nf2++) {
                int c = wn*32 + nf2*8 + 2*q;
                *(uint32_t*)&Yh[base0 + c] = pack_h2(acc[nf2][0]*oscale, acc[nf2][1]*oscale);
                *(uint32_t*)&Yh[base1 + c] = pack_h2(acc[nf2][2]*oscale, acc[nf2][3]*oscale);
            }
        }
    }

    // flush V transpose buffer: 16 h x 64 d rows of 16 l halves (32 B each)
    if (which == 0) {
        __syncthreads();
        int n = rowBase0 >> 15;                 // / (2048*16)
        int lbase = (rowBase0 >> 4) & (L_S-1);
        for (int i = tid; i < 1024; i += 256) {
            int hh = i >> 6, d = i & 63;
            const uint4* src = (const uint4*)&tb[hh*TBH + d*16];
            uint4 v0 = src[0], v1 = src[1];
            uint4* dst = (uint4*)&g_vt[(((size_t)(n*H_N + hh))*D_H + d)*L_S + lbase];
            dst[0] = v0; dst[1] = v1;
        }
    }
}

// ============================================================================
// Kernel 2: flash attention (R15 exact): fp16, q-tile 64, 128 threads
// (4 warps, m16 strips), 4 blocks/SM (regs==128 cliff — do not touch).
// P in registers (C->A identity); one __syncthreads per iteration.
// ============================================================================
#define KSTR 72
#define VSTR 72

__global__ __launch_bounds__(128, 4) void attn_mma()
{
    extern __shared__ __half smh[];
    __half* Ksb = smh;                  // [2][64*KSTR]  K: [c][e]
    __half* Vsb = smh + 2*64*KSTR;      // [2][64*VSTR]  Vt: [d][c]
    __half* Qs  = Vsb + 2*64*VSTR;      // [64*72]       Q staging

    int qt = blockIdx.x, h = blockIdx.y, n = blockIdx.z;
    int tid = threadIdx.x, warp = tid >> 5, lane = tid & 31;
    int g = lane >> 2, q = lane & 3;
    int m0 = warp * 16;

    const __half* Qg  = g_q  + ((size_t)(n*H_N + h) * L_S + qt*64) * D_H;
    const __half* Kg  = g_k  +  (size_t)(n*H_N + h) * L_S * D_H;
    const __half* Vtg = g_vt +  (size_t)(n*H_N + h) * L_S * D_H;
    const float* mb  = g_mb + n * L_S;

    uint32_t ks_u = (uint32_t)__cvta_generic_to_shared(Ksb);
    uint32_t vs_u = (uint32_t)__cvta_generic_to_shared(Vsb);
    uint32_t qs_u = (uint32_t)__cvta_generic_to_shared(Qs);

    uint32_t bRow = (lane&7) + ((lane>>4)&1)*8;
    uint32_t bCol = ((lane>>3)&1)*16;
    uint32_t addrK = ks_u + bRow*KSTR*2 + bCol;
    uint32_t addrV = vs_u + bRow*VSTR*2 + bCol;
    uint32_t aRow = (lane&7) + ((lane>>3)&1)*8;
    uint32_t aCol = (lane>>4)*16;
    uint32_t addrQ = qs_u + aRow*72*2 + aCol;

    // prefetch K/V tile 0
    {
        for (int i = tid; i < 1024; i += 128) {
            int i2 = i & 511;
            int r = i2 >> 3, c8 = (i2 & 7) << 3;
            if (i < 512) cp16(ks_u + (r*KSTR + c8)*2, Kg + r*64 + c8);
            else         cp16(vs_u + (r*VSTR + c8)*2, Vtg + (size_t)r*L_S + c8);
        }
        CP_COMMIT();
    }

    // stage Q (64 rows x 128 B)
    for (int i = tid; i < 512; i += 128) {
        int r = i >> 3, c8 = (i & 7) << 3;
        *(float4*)&Qs[r*72 + c8] = *(const float4*)&Qg[r*64 + c8];
    }
    __syncthreads();

    uint32_t qa[4][4];
    #pragma unroll
    for (int kk = 0; kk < 4; kk++)
        ldsm4(qa[kk], addrQ + m0*72*2 + kk*32);

    float O[8][4];
    #pragma unroll
    for (int nf = 0; nf < 8; nf++)
        #pragma unroll
        for (int t = 0; t < 4; t++) O[nf][t] = 0.f;
    float psacc0 = 0.f, psacc1 = 0.f;
    float sacc[8][4];

    for (int kt = 0; kt < L_S/64; kt++) {
        CP_WAIT0();
        __syncthreads();            // K/V(kt) visible; all warps past iter kt-1

        if (kt + 1 < L_S/64) {      // both prefetches overwrite kt-1 buffers
            uint32_t ko = ks_u + ((kt+1)&1) * 64*KSTR*2;
            uint32_t vo = vs_u + ((kt+1)&1) * 64*VSTR*2;
            const __half* Ksrc = Kg + (size_t)(kt+1)*4096;
            const __half* Vsrc = Vtg + (size_t)(kt+1)*64;
            for (int i = tid; i < 1024; i += 128) {
                int i2 = i & 511;
                int r = i2 >> 3, c8 = (i2 & 7) << 3;
                if (i < 512) cp16(ko + (r*KSTR + c8)*2, Ksrc + r*64 + c8);
                else         cp16(vo + (r*VSTR + c8)*2, Vsrc + (size_t)r*L_S + c8);
            }
            CP_COMMIT();
        }
        uint32_t kbuf = addrK + (kt&1) * 64*KSTR*2;
        uint32_t vbuf = addrV + (kt&1) * 64*VSTR*2;

        // ---- S = Q K^T ----
        #pragma unroll
        for (int nf = 0; nf < 8; nf++)
            #pragma unroll
            for (int t = 0; t < 4; t++) sacc[nf][t] = 0.f;
        #pragma unroll
        for (int kk = 0; kk < 4; kk++) {
            #pragma unroll
            for (int nfp = 0; nfp < 4; nfp++) {
                uint32_t kb[4];
                ldsm4(kb, kbuf + nfp*16*KSTR*2 + kk*32);
                mma16(sacc[2*nfp  ], qa[kk], kb    );
                mma16(sacc[2*nfp+1], qa[kk], kb + 2);
            }
        }

        // ---- p = exp2(s + bias), row-sum accumulate (all registers) ----
        #pragma unroll
        for (int nf = 0; nf < 8; nf++) {
            float2 m2 = *(const float2*)&mb[kt*64 + nf*8 + 2*q];
            float p0 = ex2(sacc[nf][0] + m2.x);
            float p1 = ex2(sacc[nf][1] + m2.y);
            float p2 = ex2(sacc[nf][2] + m2.x);
            float p3 = ex2(sacc[nf][3] + m2.y);
            psacc0 += p0 + p1;
            psacc1 += p2 + p3;
            sacc[nf][0] = p0; sacc[nf][1] = p1;
            sacc[nf][2] = p2; sacc[nf][3] = p3;
        }

        // ---- O += P @ V : P packed straight from sacc (C->A identity) ----
        #pragma unroll
        for (int ck = 0; ck < 4; ck++) {
            uint32_t pa[4];
            pa[0] = pack_h2(sacc[2*ck  ][0], sacc[2*ck  ][1]);
            pa[1] = pack_h2(sacc[2*ck  ][2], sacc[2*ck  ][3]);
            pa[2] = pack_h2(sacc[2*ck+1][0], sacc[2*ck+1][1]);
            pa[3] = pack_h2(sacc[2*ck+1][2], sacc[2*ck+1][3]);
            #pragma unroll
            for (int nfp = 0; nfp < 4; nfp++) {
                uint32_t vb[4];
                ldsm4(vb, vbuf + nfp*16*VSTR*2 + ck*32);
                mma16(O[2*nfp  ], pa, vb    );
                mma16(O[2*nfp+1], pa, vb + 2);
            }
        }
    }

    // ---- end reduction + fp16 epilogue ----
    psacc0 += __shfl_xor_sync(0xffffffffu, psacc0, 1);
    psacc0 += __shfl_xor_sync(0xffffffffu, psacc0, 2);
    psacc1 += __shfl_xor_sync(0xffffffffu, psacc1, 1);
    psacc1 += __shfl_xor_sync(0xffffffffu, psacc1, 2);
    float invl0 = 1.0f / psacc0;
    float invl1 = 1.0f / psacc1;
    size_t row0 = ((size_t)n*L_S + qt*64 + m0 + g    ) * E_D + h*D_H;
    size_t row1 = ((size_t)n*L_S + qt*64 + m0 + g + 8) * E_D + h*D_H;
    #pragma unroll
    for (int nf = 0; nf < 8; nf++) {
        int c = nf*8 + 2*q;
        *(uint32_t*)&g_ao[row0 + c] = pack_h2(O[nf][0]*invl0, O[nf][1]*invl0);
        *(uint32_t*)&g_ao[row1 + c] = pack_h2(O[nf][2]*invl1, O[nf][3]*invl1);
    }
}

// ============================================================================
// Kernel 3: out = A @ Wo^T + bo, fp16 m16n8k16. 128x128 tile, BK=32,
// 128 threads (2m x 2n warps, m64 x n64 warp tile).
// ============================================================================
#define GSTR 40   // halves per row (32 data + 8 pad)

__global__ __launch_bounds__(128) void out_gemm_mma(
    const float* __restrict__ bo, float* __restrict__ out)
{
    extern __shared__ __half smg[];
    __half* As = smg;               // [2][128*GSTR]
    __half* Bs = smg + 2*128*GSTR;  // [2][128*GSTR]

    int nt = blockIdx.x * 128;
    int mt = blockIdx.y * 128;
    int tid = threadIdx.x, warp = tid >> 5, lane = tid & 31;
    int g = lane >> 2, q = lane & 3;
    int wm = warp & 1, wn = warp >> 1;

    uint32_t as_u = (uint32_t)__cvta_generic_to_shared(As);
    uint32_t bs_u = (uint32_t)__cvta_generic_to_shared(Bs);

    uint32_t aRow = (lane&7) + ((lane>>3)&1)*8;
    uint32_t aCol = (lane>>4)*16;
    uint32_t addrA = as_u + aRow*GSTR*2 + aCol;
    uint32_t bRow = (lane&7) + ((lane>>4)&1)*8;
    uint32_t bCol = ((lane>>3)&1)*16;
    uint32_t addrB = bs_u + bRow*GSTR*2 + bCol;

    float acc[4][8][4];
    #pragma unroll
    for (int mi = 0; mi < 4; mi++)
        #pragma unroll
        for (int nf = 0; nf < 8; nf++)
            #pragma unroll
            for (int t = 0; t < 4; t++) acc[mi][nf][t] = 0.f;

    for (int i = tid; i < 1024; i += 128) {
        int i2 = i & 511;
        int r = i2 >> 2, c8 = (i2 & 3) << 3;
        if (i < 512) cp16(as_u + (r*GSTR + c8)*2, &g_ao[(size_t)(mt + r)*E_D + c8]);
        else         cp16(bs_u + (r*GSTR + c8)*2, &g_wo[(size_t)(nt + r)*E_D + c8]);
    }
    CP_COMMIT();

    for (int t = 0; t < E_D/32; t++) {
        CP_WAIT0();
        __syncthreads();

        if (t + 1 < E_D/32) {
            int kt = (t + 1) * 32;
            uint32_t ao  = as_u + ((t+1)&1) * 128*GSTR*2;
            uint32_t bou = bs_u + ((t+1)&1) * 128*GSTR*2;
            for (int i = tid; i < 1024; i += 128) {
                int i2 = i & 511;
                int r = i2 >> 2, c8 = (i2 & 3) << 3;
                if (i < 512) cp16(ao  + (r*GSTR + c8)*2, &g_ao[(size_t)(mt + r)*E_D + kt + c8]);
                else         cp16(bou + (r*GSTR + c8)*2, &g_wo[(size_t)(nt + r)*E_D + kt + c8]);
            }
            CP_COMMIT();
        }
        uint32_t abuf = addrA + (t&1) * 128*GSTR*2;
        uint32_t bbuf = addrB + (t&1) * 128*GSTR*2;

        #pragma unroll
        for (int kk = 0; kk < 2; kk++) {
            uint32_t a[4][4];
            #pragma unroll
            for (int mi = 0; mi < 4; mi++)
                ldsm4(a[mi], abuf + (wm*64 + mi*16)*GSTR*2 + kk*32);
            #pragma unroll
            for (int nfp = 0; nfp < 4; nfp++) {
                uint32_t b[4];
                ldsm4(b, bbuf + (wn*64 + nfp*16)*GSTR*2 + kk*32);
                #pragma unroll
                for (int mi = 0; mi < 4; mi++) {
                    mma16(acc[mi][2*nfp  ], a[mi], b    );
                    mma16(acc[mi][2*nfp+1], a[mi], b + 2);
                }
            }
        }
    }

    #pragma unroll
    for (int mi = 0; mi < 4; mi++) {
        size_t row0 = (size_t)(mt + wm*64 + mi*16 + g    ) * E_D + nt;
        size_t row1 = (size_t)(mt + wm*64 + mi*16 + g + 8) * E_D + nt;
        #pragma unroll
        for (int nf = 0; nf < 8; nf++) {
            int c = wn*64 + nf*8 + 2*q;
            float2 bb = *(const float2*)&bo[nt + c];
            *(float2*)&out[row0 + c] =
                make_float2(acc[mi][nf][0] + bb.x, acc[mi][nf][1] + bb.y);
            *(float2*)&out[row1 + c] =
                make_float2(acc[mi][nf][2] + bb.x, acc[mi][nf][3] + bb.y);
        }
    }
}

// ============================================================================
extern "C" void kernel_launch(void* const* d_in, const int* in_sizes, int n_in,
                              void* d_out, int out_size)
{
    const float* values = (const float*)d_in[0];
    const float* keysp  = (const float*)d_in[1];
    const float* query  = (const float*)d_in[2];
    const int*   mask   = (const int*)  d_in[3];
    const float* Wv     = (const float*)d_in[4];
    const float* Wk     = (const float*)d_in[5];
    const float* Wq     = (const float*)d_in[6];
    const float* Wo     = (const float*)d_in[7];
    const float* bo     = (const float*)d_in[8];
    float* out = (float*)d_out;

    // 0. merged prep
    prep_kernel<<<28 + E_D*E_D/4/256, 256>>>(Wq, Wk, Wv, Wo, mask);

    // 1. QKV projections; V transposed in-kernel (~68 KB dynamic smem)
    int smem_proj = 2*64*68*4 + 16*TBH*2;
    cudaFuncSetAttribute(proj_mma,
                         cudaFuncAttributeMaxDynamicSharedMemorySize, smem_proj);
    proj_mma<<<dim3((N_B*L_S*H_N)/256, 3), 256, smem_proj>>>(values, keysp, query);

    // 2. flash attention (R15 config: ~45 KB dynamic smem, 4 blocks/SM)
    int smem_attn = (2*64*KSTR + 2*64*VSTR + 64*72) * 2;
    cudaFuncSetAttribute(attn_mma,
                         cudaFuncAttributeMaxDynamicSharedMemorySize, smem_attn);
    attn_mma<<<dim3(L_S/64, H_N, N_B), 128, smem_attn>>>();

    // 3. output projection + bias (fp16, 40 KB dynamic smem)
    int smem_og = 4*128*GSTR * 2;
    cudaFuncSetAttribute(out_gemm_mma,
                         cudaFuncAttributeMaxDynamicSharedMemorySize, smem_og);
    out_gemm_mma<<<dim3(E_D/128, (N_B*L_S)/128), 128, smem_og>>>(bo, out);
}